// round 12
// baseline (speedup 1.0000x reference)
#include <cuda_runtime.h>
#include <math.h>
#include <stdint.h>

// ===== Model config =====
#define B_   8
#define C_   3
#define H_   384
#define W_   384
#define P_   16
#define GH_  24
#define GW_  24
#define NP_  576
#define N_   577
#define D_   768
#define NH_  12
#define HD_  64
#define MLP_ 3072
#define L_   12
#define NCLS_ 1000
#define QD_  (3*D_)          // 2304 fused qkv width

#define MROWS (B_*N_)        // 4616
#define PROWS (B_*NP_)       // 4608

// ===== Scratch =====
__device__ float g_t[B_*NP_*D_];
__device__ float g_h[MROWS*D_];
__device__ float g_y[MROWS*D_];
__device__ float g_qkv[(size_t)MROWS*QD_];
__device__ float g_o[MROWS*D_];
__device__ float g_m[(size_t)MROWS*MLP_];
__device__ float g_qkvw[(size_t)L_*D_*QD_];
__device__ float g_qkvb[L_*QD_];

__device__ __forceinline__ unsigned f2tf(float f) {
    unsigned u;
    asm("cvt.rna.tf32.f32 %0, %1;" : "=r"(u) : "f"(f));
    return u;
}
__device__ __forceinline__ float rtf(float f) { return __uint_as_float(f2tf(f)); }

__device__ __forceinline__ uint32_t smem_u32(const void* p) {
    uint32_t a;
    asm("{ .reg .u64 t; cvta.to.shared.u64 t, %1; cvt.u32.u64 %0, t; }" : "=r"(a) : "l"(p));
    return a;
}

#define MMA_TF32(acc, a0,a1,a2,a3, b0,b1) \
    asm volatile( \
        "mma.sync.aligned.m16n8k8.row.col.f32.tf32.tf32.f32 " \
        "{%0,%1,%2,%3}, {%4,%5,%6,%7}, {%8,%9}, {%0,%1,%2,%3};\n" \
        : "+f"((acc)[0]), "+f"((acc)[1]), "+f"((acc)[2]), "+f"((acc)[3]) \
        : "r"(a0), "r"(a1), "r"(a2), "r"(a3), "r"(b0), "r"(b1))

// ===== Prep: fused qkv weight concat (tf32-rounded), float4 =====
__global__ void qkv_concat_w(const float* __restrict__ qw, const float* __restrict__ kw,
                             const float* __restrict__ vw, float* __restrict__ dst) {
    int i4 = blockIdx.x * 256 + threadIdx.x;
    if (i4 >= L_*D_*QD_/4) return;
    int i = i4 * 4;
    int j = i % QD_;
    int lk = i / QD_;
    int sel = j / D_, jj = j % D_;
    const float* src = (sel == 0) ? qw : (sel == 1) ? kw : vw;
    float4 v = *reinterpret_cast<const float4*>(src + (size_t)lk * D_ + jj);
    v.x = rtf(v.x); v.y = rtf(v.y); v.z = rtf(v.z); v.w = rtf(v.w);
    *reinterpret_cast<float4*>(dst + i) = v;
}
__global__ void qkv_concat_b(const float* __restrict__ qb, const float* __restrict__ kb,
                             const float* __restrict__ vb, float* __restrict__ dst) {
    int i = blockIdx.x * 256 + threadIdx.x;
    if (i >= L_*QD_) return;
    int j = i % QD_, l = i / QD_;
    int sel = j / D_, jj = j % D_;
    const float* src = (sel == 0) ? qb : (sel == 1) ? kb : vb;
    dst[i] = src[l*D_ + jj];
}

// ===== Patchify (exact reference order), tf32-rounded out =====
__global__ void patchify_kernel(const float* __restrict__ x) {
    int idx = blockIdx.x * blockDim.x + threadIdx.x;
    if (idx >= B_*NP_*D_) return;
    const int BLK = B_*C_*GH_*GW_*P_;
    int p1 = idx / BLK;
    int r  = idx % BLK;
    int m  = r >> 4;
    int p2 = r & 15;
    int gw = m % GW_;  int m2 = m / GW_;
    int gh = m2 % GH_; int m3 = m2 / GH_;
    int c  = m3 % C_;  int bx = m3 / C_;
    g_t[idx] = rtf(x[(((size_t)(bx*C_ + c)*H_) + gh*P_ + p1)*W_ + gw*P_ + p2]);
}

__global__ void assemble_kernel(const float* __restrict__ cls, const float* __restrict__ pos) {
    int idx = blockIdx.x * blockDim.x + threadIdx.x;
    if (idx >= MROWS*D_) return;
    int d  = idx % D_;
    int rn = idx / D_;
    int n  = rn % N_;
    int b  = rn / N_;
    float v = (n == 0) ? cls[d] : g_y[((size_t)(b*NP_ + n - 1))*D_ + d];
    g_h[idx] = v + pos[n*D_ + d];
}

// ===== LayerNorm: warp per row, tf32-rounded output =====
__global__ __launch_bounds__(256) void ln_kernel(const float* __restrict__ in, float* __restrict__ out,
                          const float* __restrict__ g, const float* __restrict__ bb) {
    int wid = threadIdx.x >> 5, lane = threadIdx.x & 31;
    int row = blockIdx.x * 8 + wid;
    if (row >= MROWS) return;
    const float* p = in + (size_t)row * D_;
    float v[24];
    float s = 0.f;
    #pragma unroll
    for (int i = 0; i < 24; i++) { v[i] = p[lane + i*32]; s += v[i]; }
    #pragma unroll
    for (int o = 16; o > 0; o >>= 1) s += __shfl_xor_sync(0xffffffffu, s, o);
    float mean = s * (1.0f / D_);
    float vs = 0.f;
    #pragma unroll
    for (int i = 0; i < 24; i++) { float dx = v[i] - mean; vs += dx*dx; }
    #pragma unroll
    for (int o = 16; o > 0; o >>= 1) vs += __shfl_xor_sync(0xffffffffu, vs, o);
    float rs = rsqrtf(vs * (1.0f / D_) + 1e-5f);
    float* q = out + (size_t)row * D_;
    #pragma unroll
    for (int i = 0; i < 24; i++) {
        int c = lane + i*32;
        q[c] = rtf((v[i] - mean) * rs * g[c] + bb[c]);
    }
}

// ===== Dense TF32 GEMM: 2-stage cp.async (71KB, 2 CTAs/SM) + reg-double-buffered frags =====
// C = epi(A[M,K] @ B[K,Nc] + bias); EPI 0:+b 1:+b+res 2:gelu(+b); ROUND: tf32-round out
#define GA_SMEM (2*(128*144) + 2*(32*544))    // 71680 bytes
template<int EPI, int ROUND>
__global__ __launch_bounds__(256, 2) void tf32_gemm(
        const float* __restrict__ A, const float* __restrict__ Bw,
        const float* __restrict__ bias, const float* __restrict__ res,
        float* __restrict__ C, int M, int Nc, int K) {
    extern __shared__ char smem[];
    const uint32_t AS0 = 0, AS1 = 128*144, BS0 = 2*128*144, BS1 = 2*128*144 + 32*544;
    uint32_t sbase = smem_u32(smem);

    int tid = threadIdx.x;
    int wid = tid >> 5, lane = tid & 31;
    int gid = lane >> 2, tg = lane & 3;
    int m_w = (wid >> 2) * 64;
    int n_w = (wid & 3) * 32;
    int row0 = blockIdx.y * 128, col0 = blockIdx.x * 128;

    float acc[4][4][4] = {};

    auto load_stage = [&](int t, int bb) {
        uint32_t abase = sbase + (bb ? AS1 : AS0);
        uint32_t bbase = sbase + (bb ? BS1 : BS0);
        int kt = t << 5;
        #pragma unroll
        for (int p = 0; p < 4; p++) {
            int idx = tid + p*256;
            int r = idx >> 3, c = idx & 7;
            int gr = row0 + r;
            const float* src = A + (size_t)(gr < M ? gr : M-1)*K + kt + c*4;
            unsigned sz = (gr < M) ? 16u : 0u;
            asm volatile("cp.async.ca.shared.global [%0], [%1], 16, %2;" ::
                "r"(abase + r*144 + c*16), "l"(src), "r"(sz));
        }
        #pragma unroll
        for (int p = 0; p < 4; p++) {
            int idx = tid + p*256;
            int r = idx >> 5, c = idx & 31;
            const float* src = Bw + (size_t)(kt + r)*Nc + col0 + c*4;
            asm volatile("cp.async.ca.shared.global [%0], [%1], 16;" ::
                "r"(bbase + r*544 + c*16), "l"(src));
        }
        asm volatile("cp.async.commit_group;");
    };

    auto ldfrag = [&](const float* as, const float* bs, int ks,
                      unsigned (&af)[4][4], unsigned (&bf)[4][2]) {
        #pragma unroll
        for (int mf = 0; mf < 4; mf++) {
            int m = m_w + mf*16;
            af[mf][0] = __float_as_uint(as[(m+gid  )*36 + ks+tg  ]);
            af[mf][1] = __float_as_uint(as[(m+gid+8)*36 + ks+tg  ]);
            af[mf][2] = __float_as_uint(as[(m+gid  )*36 + ks+tg+4]);
            af[mf][3] = __float_as_uint(as[(m+gid+8)*36 + ks+tg+4]);
        }
        #pragma unroll
        for (int nf = 0; nf < 4; nf++) {
            int n = n_w + nf*8;
            bf[nf][0] = __float_as_uint(bs[(ks+tg  )*136 + n+gid]);
            bf[nf][1] = __float_as_uint(bs[(ks+tg+4)*136 + n+gid]);
        }
    };

    int KT = K >> 5;
    load_stage(0, 0);
    for (int t = 0; t < KT; t++) {
        int bb = t & 1;
        if (t + 1 < KT) {
            load_stage(t+1, bb^1);
            asm volatile("cp.async.wait_group 1;");
        } else {
            asm volatile("cp.async.wait_group 0;");
        }
        __syncthreads();
        const float* as = reinterpret_cast<const float*>(smem + (bb ? AS1 : AS0));
        const float* bs = reinterpret_cast<const float*>(smem + (bb ? BS1 : BS0));

        unsigned af[2][4][4], bf[2][4][2];
        ldfrag(as, bs, 0, af[0], bf[0]);
        #pragma unroll
        for (int ks4 = 0; ks4 < 4; ks4++) {
            int cur = ks4 & 1;
            if (ks4 < 3) ldfrag(as, bs, (ks4+1)*8, af[cur^1], bf[cur^1]);
            #pragma unroll
            for (int mf = 0; mf < 4; mf++)
                #pragma unroll
                for (int nf = 0; nf < 4; nf++)
                    MMA_TF32(acc[mf][nf], af[cur][mf][0], af[cur][mf][1],
                             af[cur][mf][2], af[cur][mf][3],
                             bf[cur][nf][0], bf[cur][nf][1]);
        }
        __syncthreads();
    }

    #pragma unroll
    for (int mf = 0; mf < 4; mf++) {
        #pragma unroll
        for (int nf = 0; nf < 4; nf++) {
            int r0 = row0 + m_w + mf*16 + gid;
            int c0 = col0 + n_w + nf*8 + tg*2;
            float b0 = bias[c0], b1 = bias[c0+1];
            #pragma unroll
            for (int half = 0; half < 2; half++) {
                int r = r0 + half*8;
                if (r < M) {
                    float v0 = acc[mf][nf][half*2+0] + b0;
                    float v1 = acc[mf][nf][half*2+1] + b1;
                    if (EPI == 1) {
                        float2 rv = *reinterpret_cast<const float2*>(res + (size_t)r*Nc + c0);
                        v0 += rv.x; v1 += rv.y;
                    }
                    if (EPI == 2) {
                        v0 = 0.5f * v0 * (1.0f + erff(v0 * 0.7071067811865475f));
                        v1 = 0.5f * v1 * (1.0f + erff(v1 * 0.7071067811865475f));
                    }
                    if (ROUND) { v0 = rtf(v0); v1 = rtf(v1); }
                    *reinterpret_cast<float2*>(C + (size_t)r*Nc + c0) = make_float2(v0, v1);
                }
            }
        }
    }
}

// ===== Fused flash attention (64 Q rows/CTA, 128 thr, online softmax) =====
#define FA_SMEM 53248
__global__ __launch_bounds__(128) void flash_attn(
        const float* __restrict__ qkv, float* __restrict__ o) {
    extern __shared__ float fs[];
    float* Ks = fs;                  // stride 68
    float* Vs = fs + 17408/4;        // stride 72
    float* Ps = fs + 35840/4;        // stride 68

    int tid = threadIdx.x;
    int wid = tid >> 5, lane = tid & 31;
    int gid = lane >> 2, tg = lane & 3;
    int z = blockIdx.y;
    int zb = z / NH_, zh = z % NH_;
    int i0 = blockIdx.x * 64;
    int r_w = wid * 16;

    #pragma unroll
    for (int p = 0; p < 8; p++) {
        int idx = tid + p*128;
        int r = idx >> 4, c4 = idx & 15;
        int gr = i0 + r; if (gr > N_-1) gr = N_-1;
        float4 v = *reinterpret_cast<const float4*>(
            qkv + (size_t)(zb*N_ + gr)*QD_ + zh*HD_ + c4*4);
        float* dst = Ps + r*68 + c4*4;
        dst[0] = v.x*0.125f; dst[1] = v.y*0.125f; dst[2] = v.z*0.125f; dst[3] = v.w*0.125f;
    }
    __syncthreads();
    unsigned qa[8][4];
    #pragma unroll
    for (int ks = 0; ks < 8; ks++) {
        qa[ks][0] = __float_as_uint(Ps[(r_w+gid  )*68 + ks*8+tg  ]);
        qa[ks][1] = __float_as_uint(Ps[(r_w+gid+8)*68 + ks*8+tg  ]);
        qa[ks][2] = __float_as_uint(Ps[(r_w+gid  )*68 + ks*8+tg+4]);
        qa[ks][3] = __float_as_uint(Ps[(r_w+gid+8)*68 + ks*8+tg+4]);
    }
    __syncthreads();

    float m0 = -1e30f, m1 = -1e30f, l0 = 0.f, l1 = 0.f;
    float oa[8][4] = {};

    for (int jt = 0; jt < 10; jt++) {
        int j0 = jt * 64;
        #pragma unroll
        for (int p = 0; p < 8; p++) {
            int idx = tid + p*128;
            int r = idx >> 4, c4 = idx & 15;
            int gj = j0 + r; if (gj > N_-1) gj = N_-1;
            const float* base = qkv + (size_t)(zb*N_ + gj)*QD_ + zh*HD_ + c4*4;
            float4 kv = *reinterpret_cast<const float4*>(base + D_);
            float4 vv = *reinterpret_cast<const float4*>(base + 2*D_);
            *reinterpret_cast<float4*>(Ks + r*68 + c4*4) = kv;
            *reinterpret_cast<float4*>(Vs + r*72 + c4*4) = vv;
        }
        __syncthreads();

        float s[8][4] = {};
        #pragma unroll
        for (int ks = 0; ks < 8; ks++) {
            #pragma unroll
            for (int nf = 0; nf < 8; nf++) {
                unsigned b0 = __float_as_uint(Ks[(nf*8+gid)*68 + ks*8+tg  ]);
                unsigned b1 = __float_as_uint(Ks[(nf*8+gid)*68 + ks*8+tg+4]);
                MMA_TF32(s[nf], qa[ks][0], qa[ks][1], qa[ks][2], qa[ks][3], b0, b1);
            }
        }
        if (j0 + 64 > N_) {
            #pragma unroll
            for (int nf = 0; nf < 8; nf++) {
                int c0 = j0 + nf*8 + tg*2;
                if (c0     >= N_) { s[nf][0] = -1e30f; s[nf][2] = -1e30f; }
                if (c0 + 1 >= N_) { s[nf][1] = -1e30f; s[nf][3] = -1e30f; }
            }
        }
        float tm0 = -1e30f, tm1 = -1e30f;
        #pragma unroll
        for (int nf = 0; nf < 8; nf++) {
            tm0 = fmaxf(tm0, fmaxf(s[nf][0], s[nf][1]));
            tm1 = fmaxf(tm1, fmaxf(s[nf][2], s[nf][3]));
        }
        #pragma unroll
        for (int off = 1; off <= 2; off <<= 1) {
            tm0 = fmaxf(tm0, __shfl_xor_sync(0xffffffffu, tm0, off));
            tm1 = fmaxf(tm1, __shfl_xor_sync(0xffffffffu, tm1, off));
        }
        float m0n = fmaxf(m0, tm0), m1n = fmaxf(m1, tm1);
        float a0 = __expf(m0 - m0n), a1 = __expf(m1 - m1n);
        float ps0 = 0.f, ps1 = 0.f;
        #pragma unroll
        for (int nf = 0; nf < 8; nf++) {
            float p0 = __expf(s[nf][0] - m0n);
            float p1 = __expf(s[nf][1] - m0n);
            float p2 = __expf(s[nf][2] - m1n);
            float p3 = __expf(s[nf][3] - m1n);
            ps0 += p0 + p1; ps1 += p2 + p3;
            float* d0 = Ps + (r_w+gid  )*68 + nf*8 + tg*2;
            float* d1 = Ps + (r_w+gid+8)*68 + nf*8 + tg*2;
            d0[0] = rtf(p0); d0[1] = rtf(p1);
            d1[0] = rtf(p2); d1[1] = rtf(p3);
            oa[nf][0] *= a0; oa[nf][1] *= a0;
            oa[nf][2] *= a1; oa[nf][3] *= a1;
        }
        #pragma unroll
        for (int off = 1; off <= 2; off <<= 1) {
            ps0 += __shfl_xor_sync(0xffffffffu, ps0, off);
            ps1 += __shfl_xor_sync(0xffffffffu, ps1, off);
        }
        l0 = l0*a0 + ps0; l1 = l1*a1 + ps1;
        m0 = m0n; m1 = m1n;
        __syncwarp();

        #pragma unroll
        for (int ks = 0; ks < 8; ks++) {
            unsigned pa0 = __float_as_uint(Ps[(r_w+gid  )*68 + ks*8+tg  ]);
            unsigned pa1 = __float_as_uint(Ps[(r_w+gid+8)*68 + ks*8+tg  ]);
            unsigned pa2 = __float_as_uint(Ps[(r_w+gid  )*68 + ks*8+tg+4]);
            unsigned pa3 = __float_as_uint(Ps[(r_w+gid+8)*68 + ks*8+tg+4]);
            #pragma unroll
            for (int nf = 0; nf < 8; nf++) {
                unsigned b0 = __float_as_uint(Vs[(ks*8+tg  )*72 + nf*8+gid]);
                unsigned b1 = __float_as_uint(Vs[(ks*8+tg+4)*72 + nf*8+gid]);
                MMA_TF32(oa[nf], pa0, pa1, pa2, pa3, b0, b1);
            }
        }
        __syncthreads();
    }

    float inv0 = 1.0f / l0, inv1 = 1.0f / l1;
    int gr0 = i0 + r_w + gid, gr1 = gr0 + 8;
    #pragma unroll
    for (int nf = 0; nf < 8; nf++) {
        int col = zh*HD_ + nf*8 + tg*2;
        if (gr0 < N_)
            *reinterpret_cast<float2*>(o + (size_t)(zb*N_ + gr0)*D_ + col) =
                make_float2(rtf(oa[nf][0]*inv0), rtf(oa[nf][1]*inv0));
        if (gr1 < N_)
            *reinterpret_cast<float2*>(o + (size_t)(zb*N_ + gr1)*D_ + col) =
                make_float2(rtf(oa[nf][2]*inv1), rtf(oa[nf][3]*inv1));
    }
}

// ===== Head =====
__global__ void head_kernel(const float* __restrict__ y, const float* __restrict__ hw,
                            const float* __restrict__ hb, float* __restrict__ out) {
    __shared__ float rowv[D_];
    int b = blockIdx.x;
    int tid = threadIdx.x;
    for (int c = tid; c < D_; c += 256) rowv[c] = y[((size_t)(b*N_))*D_ + c];
    __syncthreads();
    for (int c = tid; c < NCLS_; c += 256) {
        float s = hb[c];
        for (int d = 0; d < D_; d++) s = fmaf(rowv[d], hw[(size_t)d*NCLS_ + c], s);
        out[b*NCLS_ + c] = s;
    }
}

extern "C" void kernel_launch(void* const* d_in, const int* in_sizes, int n_in,
                              void* d_out, int out_size) {
    (void)in_sizes; (void)n_in; (void)out_size;
    const float* x       = (const float*)d_in[0];
    const float* proj_w  = (const float*)d_in[1];
    const float* proj_b  = (const float*)d_in[2];
    const float* cls_emb = (const float*)d_in[3];
    const float* pos_emb = (const float*)d_in[4];
    const float* ln1_g   = (const float*)d_in[5];
    const float* ln1_b   = (const float*)d_in[6];
    const float* qw = (const float*)d_in[7];
    const float* qb = (const float*)d_in[8];
    const float* kw = (const float*)d_in[9];
    const float* kb = (const float*)d_in[10];
    const float* vw = (const float*)d_in[11];
    const float* vb = (const float*)d_in[12];
    const float* ow = (const float*)d_in[13];
    const float* ob = (const float*)d_in[14];
    const float* ln2_g = (const float*)d_in[15];
    const float* ln2_b = (const float*)d_in[16];
    const float* fcw = (const float*)d_in[17];
    const float* fcb = (const float*)d_in[18];
    const float* pw  = (const float*)d_in[19];
    const float* pb  = (const float*)d_in[20];
    const float* lnf_g = (const float*)d_in[21];
    const float* lnf_b = (const float*)d_in[22];
    const float* head_w = (const float*)d_in[23];
    const float* head_b = (const float*)d_in[24];
    float* out = (float*)d_out;

    float *t_p, *h_p, *y_p, *qkv_p, *o_p, *m_p, *qkvw, *qkvb;
    cudaGetSymbolAddress((void**)&t_p, g_t);
    cudaGetSymbolAddress((void**)&h_p, g_h);
    cudaGetSymbolAddress((void**)&y_p, g_y);
    cudaGetSymbolAddress((void**)&qkv_p, g_qkv);
    cudaGetSymbolAddress((void**)&o_p, g_o);
    cudaGetSymbolAddress((void**)&m_p, g_m);
    cudaGetSymbolAddress((void**)&qkvw, g_qkvw);
    cudaGetSymbolAddress((void**)&qkvb, g_qkvb);

    cudaFuncSetAttribute(tf32_gemm<0,0>, cudaFuncAttributeMaxDynamicSharedMemorySize, GA_SMEM);
    cudaFuncSetAttribute(tf32_gemm<0,1>, cudaFuncAttributeMaxDynamicSharedMemorySize, GA_SMEM);
    cudaFuncSetAttribute(tf32_gemm<1,0>, cudaFuncAttributeMaxDynamicSharedMemorySize, GA_SMEM);
    cudaFuncSetAttribute(tf32_gemm<2,1>, cudaFuncAttributeMaxDynamicSharedMemorySize, GA_SMEM);
    cudaFuncSetAttribute(flash_attn, cudaFuncAttributeMaxDynamicSharedMemorySize, FA_SMEM);

    // ---- Weight prep (only fused QKV copy; O/FC1/FC2/proj weights used raw) ----
    qkv_concat_w<<<(L_*D_*QD_/4 + 255)/256, 256>>>(qw, kw, vw, qkvw);
    qkv_concat_b<<<(L_*QD_ + 255)/256, 256>>>(qb, kb, vb, qkvb);

    // ---- Patch embed ----
    patchify_kernel<<<(B_*NP_*D_ + 255)/256, 256>>>(x);
    tf32_gemm<0,0><<<dim3(D_/128, PROWS/128), 256, GA_SMEM>>>(
        t_p, proj_w, proj_b, nullptr, y_p, PROWS, D_, D_);
    assemble_kernel<<<(MROWS*D_ + 255)/256, 256>>>(cls_emb, pos_emb);

    const int gMr = (MROWS + 127) / 128;           // 37
    const dim3 gQKV(QD_/128, gMr);
    const dim3 gD(D_/128, gMr);
    const dim3 gF1(MLP_/128, gMr);
    const dim3 gFA((N_ + 63)/64, B_*NH_);          // 10 x 96
    const int lnB = (MROWS + 7) / 8;

    for (int l = 0; l < L_; l++) {
        float* qkvw_l = qkvw + (size_t)l*D_*QD_;
        const float* ow_l  = ow  + (size_t)l*D_*D_;
        const float* fcw_l = fcw + (size_t)l*D_*MLP_;
        const float* pw_l  = pw  + (size_t)l*MLP_*D_;

        ln_kernel<<<lnB, 256>>>(h_p, y_p, ln1_g + l*D_, ln1_b + l*D_);
        tf32_gemm<0,1><<<gQKV, 256, GA_SMEM>>>(y_p, qkvw_l, qkvb + l*QD_, nullptr,
                                               qkv_p, MROWS, QD_, D_);

        flash_attn<<<gFA, 128, FA_SMEM>>>(qkv_p, o_p);

        tf32_gemm<1,0><<<gD, 256, GA_SMEM>>>(o_p, ow_l, ob + l*D_, h_p, h_p, MROWS, D_, D_);

        ln_kernel<<<lnB, 256>>>(h_p, y_p, ln2_g + l*D_, ln2_b + l*D_);
        tf32_gemm<2,1><<<gF1, 256, GA_SMEM>>>(y_p, fcw_l, fcb + l*MLP_, nullptr,
                                              m_p, MROWS, MLP_, D_);
        tf32_gemm<1,0><<<gD, 256, GA_SMEM>>>(m_p, pw_l, pb + l*D_, h_p, h_p, MROWS, D_, MLP_);
    }

    ln_kernel<<<lnB, 256>>>(h_p, y_p, lnf_g, lnf_b);
    head_kernel<<<B_, 256>>>(y_p, head_w, head_b, out);
}

// round 13
// speedup vs baseline: 1.0438x; 1.0438x over previous
#include <cuda_runtime.h>
#include <math.h>
#include <stdint.h>

// ===== Model config =====
#define B_   8
#define C_   3
#define H_   384
#define W_   384
#define P_   16
#define GH_  24
#define GW_  24
#define NP_  576
#define N_   577
#define D_   768
#define NH_  12
#define HD_  64
#define MLP_ 3072
#define L_   12
#define NCLS_ 1000
#define QD_  (3*D_)          // 2304 fused qkv width

#define MROWS (B_*N_)        // 4616
#define PROWS (B_*NP_)       // 4608

// ===== Scratch =====
__device__ float g_t[B_*NP_*D_];
__device__ float g_h[MROWS*D_];
__device__ float g_y[MROWS*D_];
__device__ float g_qkv[(size_t)MROWS*QD_];
__device__ float g_o[MROWS*D_];
__device__ float g_m[(size_t)MROWS*MLP_];
__device__ float g_qkvw[(size_t)L_*D_*QD_];
__device__ float g_qkvb[L_*QD_];

__device__ __forceinline__ unsigned f2tf(float f) {
    unsigned u;
    asm("cvt.rna.tf32.f32 %0, %1;" : "=r"(u) : "f"(f));
    return u;
}
__device__ __forceinline__ float rtf(float f) { return __uint_as_float(f2tf(f)); }

__device__ __forceinline__ uint32_t smem_u32(const void* p) {
    uint32_t a;
    asm("{ .reg .u64 t; cvta.to.shared.u64 t, %1; cvt.u32.u64 %0, t; }" : "=r"(a) : "l"(p));
    return a;
}

#define MMA_TF32(acc, a0,a1,a2,a3, b0,b1) \
    asm volatile( \
        "mma.sync.aligned.m16n8k8.row.col.f32.tf32.tf32.f32 " \
        "{%0,%1,%2,%3}, {%4,%5,%6,%7}, {%8,%9}, {%0,%1,%2,%3};\n" \
        : "+f"((acc)[0]), "+f"((acc)[1]), "+f"((acc)[2]), "+f"((acc)[3]) \
        : "r"(a0), "r"(a1), "r"(a2), "r"(a3), "r"(b0), "r"(b1))

#define LDMATRIX_X4(r0,r1,r2,r3, addr) \
    asm volatile("ldmatrix.sync.aligned.m8n8.x4.shared.b16 {%0,%1,%2,%3}, [%4];" \
        : "=r"(r0), "=r"(r1), "=r"(r2), "=r"(r3) : "r"(addr))

// ===== Prep: fused qkv weight concat (tf32-rounded), float4 =====
__global__ void qkv_concat_w(const float* __restrict__ qw, const float* __restrict__ kw,
                             const float* __restrict__ vw, float* __restrict__ dst) {
    int i4 = blockIdx.x * 256 + threadIdx.x;
    if (i4 >= L_*D_*QD_/4) return;
    int i = i4 * 4;
    int j = i % QD_;
    int lk = i / QD_;
    int sel = j / D_, jj = j % D_;
    const float* src = (sel == 0) ? qw : (sel == 1) ? kw : vw;
    float4 v = *reinterpret_cast<const float4*>(src + (size_t)lk * D_ + jj);
    v.x = rtf(v.x); v.y = rtf(v.y); v.z = rtf(v.z); v.w = rtf(v.w);
    *reinterpret_cast<float4*>(dst + i) = v;
}
__global__ void qkv_concat_b(const float* __restrict__ qb, const float* __restrict__ kb,
                             const float* __restrict__ vb, float* __restrict__ dst) {
    int i = blockIdx.x * 256 + threadIdx.x;
    if (i >= L_*QD_) return;
    int j = i % QD_, l = i / QD_;
    int sel = j / D_, jj = j % D_;
    const float* src = (sel == 0) ? qb : (sel == 1) ? kb : vb;
    dst[i] = src[l*D_ + jj];
}

// ===== Patchify (exact reference order), tf32-rounded out =====
__global__ void patchify_kernel(const float* __restrict__ x) {
    int idx = blockIdx.x * blockDim.x + threadIdx.x;
    if (idx >= B_*NP_*D_) return;
    const int BLK = B_*C_*GH_*GW_*P_;
    int p1 = idx / BLK;
    int r  = idx % BLK;
    int m  = r >> 4;
    int p2 = r & 15;
    int gw = m % GW_;  int m2 = m / GW_;
    int gh = m2 % GH_; int m3 = m2 / GH_;
    int c  = m3 % C_;  int bx = m3 / C_;
    g_t[idx] = rtf(x[(((size_t)(bx*C_ + c)*H_) + gh*P_ + p1)*W_ + gw*P_ + p2]);
}

__global__ void assemble_kernel(const float* __restrict__ cls, const float* __restrict__ pos) {
    int idx = blockIdx.x * blockDim.x + threadIdx.x;
    if (idx >= MROWS*D_) return;
    int d  = idx % D_;
    int rn = idx / D_;
    int n  = rn % N_;
    int b  = rn / N_;
    float v = (n == 0) ? cls[d] : g_y[((size_t)(b*NP_ + n - 1))*D_ + d];
    g_h[idx] = v + pos[n*D_ + d];
}

// ===== LayerNorm: warp per row, tf32-rounded output =====
__global__ __launch_bounds__(256) void ln_kernel(const float* __restrict__ in, float* __restrict__ out,
                          const float* __restrict__ g, const float* __restrict__ bb) {
    int wid = threadIdx.x >> 5, lane = threadIdx.x & 31;
    int row = blockIdx.x * 8 + wid;
    if (row >= MROWS) return;
    const float* p = in + (size_t)row * D_;
    float v[24];
    float s = 0.f;
    #pragma unroll
    for (int i = 0; i < 24; i++) { v[i] = p[lane + i*32]; s += v[i]; }
    #pragma unroll
    for (int o = 16; o > 0; o >>= 1) s += __shfl_xor_sync(0xffffffffu, s, o);
    float mean = s * (1.0f / D_);
    float vs = 0.f;
    #pragma unroll
    for (int i = 0; i < 24; i++) { float dx = v[i] - mean; vs += dx*dx; }
    #pragma unroll
    for (int o = 16; o > 0; o >>= 1) vs += __shfl_xor_sync(0xffffffffu, vs, o);
    float rs = rsqrtf(vs * (1.0f / D_) + 1e-5f);
    float* q = out + (size_t)row * D_;
    #pragma unroll
    for (int i = 0; i < 24; i++) {
        int c = lane + i*32;
        q[c] = rtf((v[i] - mean) * rs * g[c] + bb[c]);
    }
}

// ===== Dense TF32 GEMM: 2-stage cp.async + ldmatrix A fragments =====
// C = epi(A[M,K] @ B[K,Nc] + bias); EPI 0:+b 1:+b+res 2:gelu(+b); ROUND: tf32-round out
#define GA_SMEM (2*(128*144) + 2*(32*544))    // 71680 bytes
template<int EPI, int ROUND>
__global__ __launch_bounds__(256, 2) void tf32_gemm(
        const float* __restrict__ A, const float* __restrict__ Bw,
        const float* __restrict__ bias, const float* __restrict__ res,
        float* __restrict__ C, int M, int Nc, int K) {
    extern __shared__ char smem[];
    const uint32_t AS0 = 0, AS1 = 128*144, BS0 = 2*128*144, BS1 = 2*128*144 + 32*544;
    uint32_t sbase = smem_u32(smem);

    int tid = threadIdx.x;
    int wid = tid >> 5, lane = tid & 31;
    int gid = lane >> 2, tg = lane & 3;
    int m_w = (wid >> 2) * 64;
    int n_w = (wid & 3) * 32;
    int row0 = blockIdx.y * 128, col0 = blockIdx.x * 128;

    // ldmatrix lane mapping: matrix i = lane/8, row-in-matrix = lane%8
    //   mat 0: (m+row, k+0..3)   mat 1: (m+8+row, k+0..3)
    //   mat 2: (m+row, k+4..7)   mat 3: (m+8+row, k+4..7)
    int lm_mat = lane >> 3, lm_row = lane & 7;
    uint32_t lm_off = (uint32_t)(((lm_mat & 1) * 8 + lm_row) * 144 + (lm_mat >> 1) * 16);

    float acc[4][4][4] = {};

    auto load_stage = [&](int t, int bb) {
        uint32_t abase = sbase + (bb ? AS1 : AS0);
        uint32_t bbase = sbase + (bb ? BS1 : BS0);
        int kt = t << 5;
        #pragma unroll
        for (int p = 0; p < 4; p++) {
            int idx = tid + p*256;
            int r = idx >> 3, c = idx & 7;
            int gr = row0 + r;
            const float* src = A + (size_t)(gr < M ? gr : M-1)*K + kt + c*4;
            unsigned sz = (gr < M) ? 16u : 0u;
            asm volatile("cp.async.ca.shared.global [%0], [%1], 16, %2;" ::
                "r"(abase + r*144 + c*16), "l"(src), "r"(sz));
        }
        #pragma unroll
        for (int p = 0; p < 4; p++) {
            int idx = tid + p*256;
            int r = idx >> 5, c = idx & 31;
            const float* src = Bw + (size_t)(kt + r)*Nc + col0 + c*4;
            asm volatile("cp.async.ca.shared.global [%0], [%1], 16;" ::
                "r"(bbase + r*544 + c*16), "l"(src));
        }
        asm volatile("cp.async.commit_group;");
    };

    int KT = K >> 5;
    load_stage(0, 0);
    for (int t = 0; t < KT; t++) {
        int bb = t & 1;
        if (t + 1 < KT) {
            load_stage(t+1, bb^1);
            asm volatile("cp.async.wait_group 1;");
        } else {
            asm volatile("cp.async.wait_group 0;");
        }
        __syncthreads();
        uint32_t a_sm = sbase + (bb ? AS1 : AS0) + (uint32_t)(m_w*144) + lm_off;
        const float* bs = reinterpret_cast<const float*>(smem + (bb ? BS1 : BS0));
        #pragma unroll
        for (int ks = 0; ks < 32; ks += 8) {
            unsigned af[4][4], bf[4][2];
            #pragma unroll
            for (int mf = 0; mf < 4; mf++)
                LDMATRIX_X4(af[mf][0], af[mf][1], af[mf][2], af[mf][3],
                            a_sm + (uint32_t)(mf*16*144 + ks*4));
            #pragma unroll
            for (int nf = 0; nf < 4; nf++) {
                int n = n_w + nf*8;
                bf[nf][0] = __float_as_uint(bs[(ks+tg  )*136 + n+gid]);
                bf[nf][1] = __float_as_uint(bs[(ks+tg+4)*136 + n+gid]);
            }
            #pragma unroll
            for (int mf = 0; mf < 4; mf++)
                #pragma unroll
                for (int nf = 0; nf < 4; nf++)
                    MMA_TF32(acc[mf][nf], af[mf][0], af[mf][1], af[mf][2], af[mf][3],
                             bf[nf][0], bf[nf][1]);
        }
        __syncthreads();
    }

    #pragma unroll
    for (int mf = 0; mf < 4; mf++) {
        #pragma unroll
        for (int nf = 0; nf < 4; nf++) {
            int r0 = row0 + m_w + mf*16 + gid;
            int c0 = col0 + n_w + nf*8 + tg*2;
            float b0 = bias[c0], b1 = bias[c0+1];
            #pragma unroll
            for (int half = 0; half < 2; half++) {
                int r = r0 + half*8;
                if (r < M) {
                    float v0 = acc[mf][nf][half*2+0] + b0;
                    float v1 = acc[mf][nf][half*2+1] + b1;
                    if (EPI == 1) {
                        float2 rv = *reinterpret_cast<const float2*>(res + (size_t)r*Nc + c0);
                        v0 += rv.x; v1 += rv.y;
                    }
                    if (EPI == 2) {
                        v0 = 0.5f * v0 * (1.0f + erff(v0 * 0.7071067811865475f));
                        v1 = 0.5f * v1 * (1.0f + erff(v1 * 0.7071067811865475f));
                    }
                    if (ROUND) { v0 = rtf(v0); v1 = rtf(v1); }
                    *reinterpret_cast<float2*>(C + (size_t)r*Nc + c0) = make_float2(v0, v1);
                }
            }
        }
    }
}

// ===== Fused flash attention (64 Q rows/CTA, 128 thr, online softmax) =====
#define FA_SMEM 53248
__global__ __launch_bounds__(128) void flash_attn(
        const float* __restrict__ qkv, float* __restrict__ o) {
    extern __shared__ float fs[];
    float* Ks = fs;                  // stride 68
    float* Vs = fs + 17408/4;        // stride 72
    float* Ps = fs + 35840/4;        // stride 68

    int tid = threadIdx.x;
    int wid = tid >> 5, lane = tid & 31;
    int gid = lane >> 2, tg = lane & 3;
    int z = blockIdx.y;
    int zb = z / NH_, zh = z % NH_;
    int i0 = blockIdx.x * 64;
    int r_w = wid * 16;

    #pragma unroll
    for (int p = 0; p < 8; p++) {
        int idx = tid + p*128;
        int r = idx >> 4, c4 = idx & 15;
        int gr = i0 + r; if (gr > N_-1) gr = N_-1;
        float4 v = *reinterpret_cast<const float4*>(
            qkv + (size_t)(zb*N_ + gr)*QD_ + zh*HD_ + c4*4);
        float* dst = Ps + r*68 + c4*4;
        dst[0] = v.x*0.125f; dst[1] = v.y*0.125f; dst[2] = v.z*0.125f; dst[3] = v.w*0.125f;
    }
    __syncthreads();
    unsigned qa[8][4];
    #pragma unroll
    for (int ks = 0; ks < 8; ks++) {
        qa[ks][0] = __float_as_uint(Ps[(r_w+gid  )*68 + ks*8+tg  ]);
        qa[ks][1] = __float_as_uint(Ps[(r_w+gid+8)*68 + ks*8+tg  ]);
        qa[ks][2] = __float_as_uint(Ps[(r_w+gid  )*68 + ks*8+tg+4]);
        qa[ks][3] = __float_as_uint(Ps[(r_w+gid+8)*68 + ks*8+tg+4]);
    }
    __syncthreads();

    float m0 = -1e30f, m1 = -1e30f, l0 = 0.f, l1 = 0.f;
    float oa[8][4] = {};

    for (int jt = 0; jt < 10; jt++) {
        int j0 = jt * 64;
        #pragma unroll
        for (int p = 0; p < 8; p++) {
            int idx = tid + p*128;
            int r = idx >> 4, c4 = idx & 15;
            int gj = j0 + r; if (gj > N_-1) gj = N_-1;
            const float* base = qkv + (size_t)(zb*N_ + gj)*QD_ + zh*HD_ + c4*4;
            float4 kv = *reinterpret_cast<const float4*>(base + D_);
            float4 vv = *reinterpret_cast<const float4*>(base + 2*D_);
            *reinterpret_cast<float4*>(Ks + r*68 + c4*4) = kv;
            *reinterpret_cast<float4*>(Vs + r*72 + c4*4) = vv;
        }
        __syncthreads();

        float s[8][4] = {};
        #pragma unroll
        for (int ks = 0; ks < 8; ks++) {
            #pragma unroll
            for (int nf = 0; nf < 8; nf++) {
                unsigned b0 = __float_as_uint(Ks[(nf*8+gid)*68 + ks*8+tg  ]);
                unsigned b1 = __float_as_uint(Ks[(nf*8+gid)*68 + ks*8+tg+4]);
                MMA_TF32(s[nf], qa[ks][0], qa[ks][1], qa[ks][2], qa[ks][3], b0, b1);
            }
        }
        if (j0 + 64 > N_) {
            #pragma unroll
            for (int nf = 0; nf < 8; nf++) {
                int c0 = j0 + nf*8 + tg*2;
                if (c0     >= N_) { s[nf][0] = -1e30f; s[nf][2] = -1e30f; }
                if (c0 + 1 >= N_) { s[nf][1] = -1e30f; s[nf][3] = -1e30f; }
            }
        }
        float tm0 = -1e30f, tm1 = -1e30f;
        #pragma unroll
        for (int nf = 0; nf < 8; nf++) {
            tm0 = fmaxf(tm0, fmaxf(s[nf][0], s[nf][1]));
            tm1 = fmaxf(tm1, fmaxf(s[nf][2], s[nf][3]));
        }
        #pragma unroll
        for (int off = 1; off <= 2; off <<= 1) {
            tm0 = fmaxf(tm0, __shfl_xor_sync(0xffffffffu, tm0, off));
            tm1 = fmaxf(tm1, __shfl_xor_sync(0xffffffffu, tm1, off));
        }
        float m0n = fmaxf(m0, tm0), m1n = fmaxf(m1, tm1);
        float a0 = __expf(m0 - m0n), a1 = __expf(m1 - m1n);
        float ps0 = 0.f, ps1 = 0.f;
        #pragma unroll
        for (int nf = 0; nf < 8; nf++) {
            float p0 = __expf(s[nf][0] - m0n);
            float p1 = __expf(s[nf][1] - m0n);
            float p2 = __expf(s[nf][2] - m1n);
            float p3 = __expf(s[nf][3] - m1n);
            ps0 += p0 + p1; ps1 += p2 + p3;
            float* d0 = Ps + (r_w+gid  )*68 + nf*8 + tg*2;
            float* d1 = Ps + (r_w+gid+8)*68 + nf*8 + tg*2;
            d0[0] = rtf(p0); d0[1] = rtf(p1);
            d1[0] = rtf(p2); d1[1] = rtf(p3);
            oa[nf][0] *= a0; oa[nf][1] *= a0;
            oa[nf][2] *= a1; oa[nf][3] *= a1;
        }
        #pragma unroll
        for (int off = 1; off <= 2; off <<= 1) {
            ps0 += __shfl_xor_sync(0xffffffffu, ps0, off);
            ps1 += __shfl_xor_sync(0xffffffffu, ps1, off);
        }
        l0 = l0*a0 + ps0; l1 = l1*a1 + ps1;
        m0 = m0n; m1 = m1n;
        __syncwarp();

        #pragma unroll
        for (int ks = 0; ks < 8; ks++) {
            unsigned pa0 = __float_as_uint(Ps[(r_w+gid  )*68 + ks*8+tg  ]);
            unsigned pa1 = __float_as_uint(Ps[(r_w+gid+8)*68 + ks*8+tg  ]);
            unsigned pa2 = __float_as_uint(Ps[(r_w+gid  )*68 + ks*8+tg+4]);
            unsigned pa3 = __float_as_uint(Ps[(r_w+gid+8)*68 + ks*8+tg+4]);
            #pragma unroll
            for (int nf = 0; nf < 8; nf++) {
                unsigned b0 = __float_as_uint(Vs[(ks*8+tg  )*72 + nf*8+gid]);
                unsigned b1 = __float_as_uint(Vs[(ks*8+tg+4)*72 + nf*8+gid]);
                MMA_TF32(oa[nf], pa0, pa1, pa2, pa3, b0, b1);
            }
        }
        __syncthreads();
    }

    float inv0 = 1.0f / l0, inv1 = 1.0f / l1;
    int gr0 = i0 + r_w + gid, gr1 = gr0 + 8;
    #pragma unroll
    for (int nf = 0; nf < 8; nf++) {
        int col = zh*HD_ + nf*8 + tg*2;
        if (gr0 < N_)
            *reinterpret_cast<float2*>(o + (size_t)(zb*N_ + gr0)*D_ + col) =
                make_float2(rtf(oa[nf][0]*inv0), rtf(oa[nf][1]*inv0));
        if (gr1 < N_)
            *reinterpret_cast<float2*>(o + (size_t)(zb*N_ + gr1)*D_ + col) =
                make_float2(rtf(oa[nf][2]*inv1), rtf(oa[nf][3]*inv1));
    }
}

// ===== Head =====
__global__ void head_kernel(const float* __restrict__ y, const float* __restrict__ hw,
                            const float* __restrict__ hb, float* __restrict__ out) {
    __shared__ float rowv[D_];
    int b = blockIdx.x;
    int tid = threadIdx.x;
    for (int c = tid; c < D_; c += 256) rowv[c] = y[((size_t)(b*N_))*D_ + c];
    __syncthreads();
    for (int c = tid; c < NCLS_; c += 256) {
        float s = hb[c];
        for (int d = 0; d < D_; d++) s = fmaf(rowv[d], hw[(size_t)d*NCLS_ + c], s);
        out[b*NCLS_ + c] = s;
    }
}

extern "C" void kernel_launch(void* const* d_in, const int* in_sizes, int n_in,
                              void* d_out, int out_size) {
    (void)in_sizes; (void)n_in; (void)out_size;
    const float* x       = (const float*)d_in[0];
    const float* proj_w  = (const float*)d_in[1];
    const float* proj_b  = (const float*)d_in[2];
    const float* cls_emb = (const float*)d_in[3];
    const float* pos_emb = (const float*)d_in[4];
    const float* ln1_g   = (const float*)d_in[5];
    const float* ln1_b   = (const float*)d_in[6];
    const float* qw = (const float*)d_in[7];
    const float* qb = (const float*)d_in[8];
    const float* kw = (const float*)d_in[9];
    const float* kb = (const float*)d_in[10];
    const float* vw = (const float*)d_in[11];
    const float* vb = (const float*)d_in[12];
    const float* ow = (const float*)d_in[13];
    const float* ob = (const float*)d_in[14];
    const float* ln2_g = (const float*)d_in[15];
    const float* ln2_b = (const float*)d_in[16];
    const float* fcw = (const float*)d_in[17];
    const float* fcb = (const float*)d_in[18];
    const float* pw  = (const float*)d_in[19];
    const float* pb  = (const float*)d_in[20];
    const float* lnf_g = (const float*)d_in[21];
    const float* lnf_b = (const float*)d_in[22];
    const float* head_w = (const float*)d_in[23];
    const float* head_b = (const float*)d_in[24];
    float* out = (float*)d_out;

    float *t_p, *h_p, *y_p, *qkv_p, *o_p, *m_p, *qkvw, *qkvb;
    cudaGetSymbolAddress((void**)&t_p, g_t);
    cudaGetSymbolAddress((void**)&h_p, g_h);
    cudaGetSymbolAddress((void**)&y_p, g_y);
    cudaGetSymbolAddress((void**)&qkv_p, g_qkv);
    cudaGetSymbolAddress((void**)&o_p, g_o);
    cudaGetSymbolAddress((void**)&m_p, g_m);
    cudaGetSymbolAddress((void**)&qkvw, g_qkvw);
    cudaGetSymbolAddress((void**)&qkvb, g_qkvb);

    cudaFuncSetAttribute(tf32_gemm<0,0>, cudaFuncAttributeMaxDynamicSharedMemorySize, GA_SMEM);
    cudaFuncSetAttribute(tf32_gemm<0,1>, cudaFuncAttributeMaxDynamicSharedMemorySize, GA_SMEM);
    cudaFuncSetAttribute(tf32_gemm<1,0>, cudaFuncAttributeMaxDynamicSharedMemorySize, GA_SMEM);
    cudaFuncSetAttribute(tf32_gemm<2,1>, cudaFuncAttributeMaxDynamicSharedMemorySize, GA_SMEM);
    cudaFuncSetAttribute(flash_attn, cudaFuncAttributeMaxDynamicSharedMemorySize, FA_SMEM);

    // ---- Weight prep (only fused QKV copy; O/FC1/FC2/proj weights used raw) ----
    qkv_concat_w<<<(L_*D_*QD_/4 + 255)/256, 256>>>(qw, kw, vw, qkvw);
    qkv_concat_b<<<(L_*QD_ + 255)/256, 256>>>(qb, kb, vb, qkvb);

    // ---- Patch embed ----
    patchify_kernel<<<(B_*NP_*D_ + 255)/256, 256>>>(x);
    tf32_gemm<0,0><<<dim3(D_/128, PROWS/128), 256, GA_SMEM>>>(
        t_p, proj_w, proj_b, nullptr, y_p, PROWS, D_, D_);
    assemble_kernel<<<(MROWS*D_ + 255)/256, 256>>>(cls_emb, pos_emb);

    const int gMr = (MROWS + 127) / 128;           // 37
    const dim3 gQKV(QD_/128, gMr);
    const dim3 gD(D_/128, gMr);
    const dim3 gF1(MLP_/128, gMr);
    const dim3 gFA((N_ + 63)/64, B_*NH_);          // 10 x 96
    const int lnB = (MROWS + 7) / 8;

    for (int l = 0; l < L_; l++) {
        float* qkvw_l = qkvw + (size_t)l*D_*QD_;
        const float* ow_l  = ow  + (size_t)l*D_*D_;
        const float* fcw_l = fcw + (size_t)l*D_*MLP_;
        const float* pw_l  = pw  + (size_t)l*MLP_*D_;

        ln_kernel<<<lnB, 256>>>(h_p, y_p, ln1_g + l*D_, ln1_b + l*D_);
        tf32_gemm<0,1><<<gQKV, 256, GA_SMEM>>>(y_p, qkvw_l, qkvb + l*QD_, nullptr,
                                               qkv_p, MROWS, QD_, D_);

        flash_attn<<<gFA, 128, FA_SMEM>>>(qkv_p, o_p);

        tf32_gemm<1,0><<<gD, 256, GA_SMEM>>>(o_p, ow_l, ob + l*D_, h_p, h_p, MROWS, D_, D_);

        ln_kernel<<<lnB, 256>>>(h_p, y_p, ln2_g + l*D_, ln2_b + l*D_);
        tf32_gemm<2,1><<<gF1, 256, GA_SMEM>>>(y_p, fcw_l, fcb + l*MLP_, nullptr,
                                              m_p, MROWS, MLP_, D_);
        tf32_gemm<1,0><<<gD, 256, GA_SMEM>>>(m_p, pw_l, pb + l*D_, h_p, h_p, MROWS, D_, MLP_);
    }

    ln_kernel<<<lnB, 256>>>(h_p, y_p, lnf_g, lnf_b);
    head_kernel<<<B_, 256>>>(y_p, head_w, head_b, out);
}